// round 3
// baseline (speedup 1.0000x reference)
#include <cuda_runtime.h>
#include <math.h>

#define BATCH 2
#define CH    512
#define HH    128
#define WW    128
#define NPIX  (HH*WW)        // 16384
#define MROWS (BATCH*NPIX)   // 32768
#define HEADS 8
#define HDIM  64
#define PTS   4
#define LNUM  6

// ---------------- device scratch (no allocations allowed) ----------------
static __device__ float g_q   [MROWS*CH];
static __device__ float g_qpos[MROWS*CH];
static __device__ float g_feat[MROWS*CH];
static __device__ float g_v   [MROWS*CH];
static __device__ float g_b1  [MROWS*CH];
static __device__ float g_b2  [MROWS*CH];
static __device__ float g_off [MROWS*HEADS*PTS*2];
static __device__ float g_awl [MROWS*HEADS*PTS];
static __device__ float g_ref [MROWS*2];
static __device__ int   g_valid [MROWS];
static __device__ int   g_order [MROWS];
static __device__ int   g_validp[MROWS];
static __device__ int   g_rank  [MROWS];

// ---------------- validity mask: all 512 channels nonzero ----------------
__global__ void k_validity(const float* __restrict__ lidar) {
    int n = blockIdx.x * blockDim.x + threadIdx.x;
    int b = blockIdx.y;
    if (n >= NPIX) return;
    const float* p = lidar + (size_t)b * CH * NPIX + n;
    int ok = 1;
    #pragma unroll 8
    for (int c = 0; c < CH; c++) ok &= (p[(size_t)c * NPIX] != 0.0f);
    g_valid[b * NPIX + n] = ok;
}

// ---------------- stable partition (valid-first) via block scan ----------------
__global__ void k_scan() {
    int b = blockIdx.x;
    int tid = threadIdx.x;
    __shared__ int sd[1024];
    __shared__ int sbase;
    if (tid == 0) sbase = 0;
    __syncthreads();
    for (int c = 0; c < NPIX / 1024; c++) {
        int i = c * 1024 + tid;
        int v = g_valid[b * NPIX + i];
        sd[tid] = v;
        __syncthreads();
        for (int off = 1; off < 1024; off <<= 1) {
            int t = (tid >= off) ? sd[tid - off] : 0;
            __syncthreads();
            sd[tid] += t;
            __syncthreads();
        }
        g_rank[b * NPIX + i] = sbase + sd[tid] - v;   // exclusive rank among valid
        __syncthreads();
        if (tid == 1023) sbase += sd[1023];
        __syncthreads();
    }
    int total = sbase;
    for (int c = 0; c < NPIX / 1024; c++) {
        int i = c * 1024 + tid;
        int v = g_valid[b * NPIX + i];
        int r = g_rank[b * NPIX + i];
        int pos = v ? r : (total + i - r);
        g_order [b * NPIX + pos] = i;
        g_validp[b * NPIX + pos] = v;
    }
}

// ---------------- packed reference points ----------------
__global__ void k_ref() {
    int i = blockIdx.x * blockDim.x + threadIdx.x;
    if (i >= MROWS) return;
    int n = g_order[i];
    float m = g_validp[i] ? 1.0f : 0.0f;
    g_ref[i * 2 + 0] = ((float)(n % WW) / (float)WW) * m;
    g_ref[i * 2 + 1] = ((float)(n / WW) / (float)HH) * m;
}

// ---------------- (B,C,N) -> packed (B,N,C) gather / plain transpose ----------------
__global__ void k_pack(const float* __restrict__ src, float* __restrict__ dst, int usePerm) {
    int idx = blockIdx.x * blockDim.x + threadIdx.x;
    if (idx >= MROWS * CH) return;
    int c   = idx & (CH - 1);
    int row = idx >> 9;            // b*NPIX + p
    int b   = row >> 14;
    int p   = row & (NPIX - 1);
    int n   = usePerm ? g_order[row] : p;
    float val = src[((size_t)b * CH + c) * NPIX + n];
    if (usePerm && !g_validp[row]) val = 0.0f;
    dst[idx] = val;
}

// ---------------- scatter packed q back to dense (B,C,H,W) ----------------
__global__ void k_scatter(float* __restrict__ out) {
    int idx = blockIdx.x * blockDim.x + threadIdx.x;
    if (idx >= MROWS * CH) return;
    int c   = idx & (CH - 1);
    int row = idx >> 9;
    int b   = row >> 14;
    int n   = g_order[row];
    float val = g_validp[row] ? g_q[idx] : 0.0f;
    out[((size_t)b * CH + c) * NPIX + n] = val;
}

// ---------------- positional embedding: ref@peW1 -> BN(eval) -> relu ----------------
__global__ void k_pe(const float* __restrict__ peW1, const float* __restrict__ g,
                     const float* __restrict__ bb, const float* __restrict__ m,
                     const float* __restrict__ vv) {
    int idx = blockIdx.x * blockDim.x + threadIdx.x;
    if (idx >= MROWS * CH) return;
    int c   = idx & (CH - 1);
    int row = idx >> 9;
    float rx = g_ref[row * 2], ry = g_ref[row * 2 + 1];
    float p = rx * peW1[c] + ry * peW1[CH + c];
    p = (p - m[c]) * rsqrtf(vv[c] + 1e-5f) * g[c] + bb[c];
    g_b1[idx] = fmaxf(p, 0.0f);
}

// ---------------- fp32 SGEMM 128x128x8, 256 thr, 8x8/thread ----------------
// C[M,N] = (A (+A2)) @ Bw[K,N] (+bias) (+Res) (relu?)   M = MROWS (multiple of 128)
template<int ADD2, int BIAS, int RES, int RELU>
__global__ __launch_bounds__(256)
void k_gemm(const float* __restrict__ A, const float* __restrict__ A2,
            const float* __restrict__ Bw, const float* __restrict__ bias,
            const float* __restrict__ Res, float* __restrict__ Cc,
            int Ncols, int Kdim) {
    __shared__ float As[8][128];
    __shared__ float Bs[8][128];
    int tid  = threadIdx.x;
    int arow = tid >> 1, acol = (tid & 1) << 2;
    int brl  = tid >> 5, bcl  = (tid & 31) << 2;
    int tr   = (tid >> 4) << 3, tc = (tid & 15) << 3;
    size_t aBase = ((size_t)blockIdx.y * 128 + arow) * (size_t)Kdim + acol;
    int colG = blockIdx.x * 128 + bcl;

    float acc[8][8];
    #pragma unroll
    for (int i = 0; i < 8; i++)
        #pragma unroll
        for (int j = 0; j < 8; j++) acc[i][j] = 0.0f;

    for (int k0 = 0; k0 < Kdim; k0 += 8) {
        float4 av = *(const float4*)(A + aBase + k0);
        if (ADD2) {
            float4 a2 = *(const float4*)(A2 + aBase + k0);
            av.x += a2.x; av.y += a2.y; av.z += a2.z; av.w += a2.w;
        }
        As[acol + 0][arow] = av.x; As[acol + 1][arow] = av.y;
        As[acol + 2][arow] = av.z; As[acol + 3][arow] = av.w;
        float4 bv = make_float4(0.f, 0.f, 0.f, 0.f);
        if (colG < Ncols) bv = *(const float4*)(Bw + (size_t)(k0 + brl) * Ncols + colG);
        *(float4*)&Bs[brl][bcl] = bv;
        __syncthreads();
        #pragma unroll
        for (int kk = 0; kk < 8; kk++) {
            float ar[8], br[8];
            *(float4*)(ar)     = *(float4*)&As[kk][tr];
            *(float4*)(ar + 4) = *(float4*)&As[kk][tr + 4];
            *(float4*)(br)     = *(float4*)&Bs[kk][tc];
            *(float4*)(br + 4) = *(float4*)&Bs[kk][tc + 4];
            #pragma unroll
            for (int i = 0; i < 8; i++)
                #pragma unroll
                for (int j = 0; j < 8; j++) acc[i][j] += ar[i] * br[j];
        }
        __syncthreads();
    }
    #pragma unroll
    for (int i = 0; i < 8; i++) {
        size_t row = (size_t)blockIdx.y * 128 + tr + i;
        #pragma unroll
        for (int j = 0; j < 8; j++) {
            int col = blockIdx.x * 128 + tc + j;
            if (col < Ncols) {
                float v = acc[i][j];
                if (BIAS) v += bias[col];
                if (RES)  v += Res[row * (size_t)Ncols + col];
                if (RELU) v = fmaxf(v, 0.0f);
                Cc[row * (size_t)Ncols + col] = v;
            }
        }
    }
}

// ---------------- LayerNorm over C=512, one block per row ----------------
__global__ void k_ln(const float* __restrict__ y, const float* __restrict__ g,
                     const float* __restrict__ bb, float* __restrict__ out) {
    int row = blockIdx.x;
    int tid = threadIdx.x;   // 128
    float4 v = *(const float4*)(y + (size_t)row * CH + tid * 4);
    float s  = v.x + v.y + v.z + v.w;
    float sq = v.x * v.x + v.y * v.y + v.z * v.z + v.w * v.w;
    for (int o = 16; o > 0; o >>= 1) {
        s  += __shfl_down_sync(~0u, s,  o);
        sq += __shfl_down_sync(~0u, sq, o);
    }
    __shared__ float ss[4], ssq[4];
    __shared__ float smu, sinv;
    int wid = tid >> 5, lane = tid & 31;
    if (lane == 0) { ss[wid] = s; ssq[wid] = sq; }
    __syncthreads();
    if (tid == 0) {
        float S  = ss[0] + ss[1] + ss[2] + ss[3];
        float SQ = ssq[0] + ssq[1] + ssq[2] + ssq[3];
        float mu = S / CH;
        float var = SQ / CH - mu * mu;
        smu = mu; sinv = rsqrtf(var + 1e-5f);
    }
    __syncthreads();
    float mu = smu, inv = sinv;
    float4 gg = *(const float4*)(g  + tid * 4);
    float4 bv = *(const float4*)(bb + tid * 4);
    float4 o;
    o.x = (v.x - mu) * inv * gg.x + bv.x;
    o.y = (v.y - mu) * inv * gg.y + bv.y;
    o.z = (v.z - mu) * inv * gg.z + bv.z;
    o.w = (v.w - mu) * inv * gg.w + bv.w;
    *(float4*)(out + (size_t)row * CH + tid * 4) = o;
}

// ---------------- deformable sampling + softmax, one warp per (token, head) ----------------
__global__ void k_sample() {
    int row  = blockIdx.x;              // b*NPIX + p
    int b    = row >> 14;
    int h    = threadIdx.x >> 5;
    int lane = threadIdx.x & 31;
    float refx = g_ref[row * 2], refy = g_ref[row * 2 + 1];

    float l0 = g_awl[row * 32 + h * 4 + 0];
    float l1 = g_awl[row * 32 + h * 4 + 1];
    float l2 = g_awl[row * 32 + h * 4 + 2];
    float l3 = g_awl[row * 32 + h * 4 + 3];
    float mx = fmaxf(fmaxf(l0, l1), fmaxf(l2, l3));
    float e0 = expf(l0 - mx), e1 = expf(l1 - mx), e2 = expf(l2 - mx), e3 = expf(l3 - mx);
    float inv = 1.0f / (e0 + e1 + e2 + e3);

    const float* vb = g_v + (size_t)b * NPIX * CH + h * HDIM;
    float acc0 = 0.f, acc1 = 0.f;
    #pragma unroll
    for (int p = 0; p < 4; p++) {
        float wgt = (p == 0 ? e0 : p == 1 ? e1 : p == 2 ? e2 : e3) * inv;
        float ox = g_off[row * 64 + h * 8 + p * 2 + 0];
        float oy = g_off[row * 64 + h * 8 + p * 2 + 1];
        float x = refx * (float)WW + ox - 0.5f;
        float y = refy * (float)HH + oy - 0.5f;
        float x0f = floorf(x), y0f = floorf(y);
        float wx = x - x0f, wy = y - y0f;
        int x0 = (int)x0f, y0 = (int)y0f;
        #pragma unroll
        for (int cy = 0; cy < 2; cy++) {
            #pragma unroll
            for (int cx = 0; cx < 2; cx++) {
                int xi = x0 + cx, yi = y0 + cy;
                float wc = (cx ? wx : 1.0f - wx) * (cy ? wy : 1.0f - wy);
                float inb = (xi >= 0 && xi < WW && yi >= 0 && yi < HH) ? 1.0f : 0.0f;
                int xc = min(max(xi, 0), WW - 1);
                int yc = min(max(yi, 0), HH - 1);
                size_t base = (size_t)(yc * WW + xc) * CH;
                float w = wgt * wc * inb;
                acc0 += w * vb[base + lane];
                acc1 += w * vb[base + lane + 32];
            }
        }
    }
    g_b1[(size_t)row * CH + h * HDIM + lane]      = acc0;
    g_b1[(size_t)row * CH + h * HDIM + lane + 32] = acc1;
}

// ---------------- host ----------------
extern "C" void kernel_launch(void* const* d_in, const int* in_sizes, int n_in,
                              void* d_out, int out_size) {
    const float* bev   = (const float*)d_in[0];
    const float* lidar = (const float*)d_in[1];
    const float* Wv    = (const float*)d_in[2];
    const float* bv    = (const float*)d_in[3];
    const float* Woff  = (const float*)d_in[4];
    const float* boff  = (const float*)d_in[5];
    const float* Waw   = (const float*)d_in[6];
    const float* baw   = (const float*)d_in[7];
    const float* Wout  = (const float*)d_in[8];
    const float* bout  = (const float*)d_in[9];
    const float* ln1g  = (const float*)d_in[10];
    const float* ln1b  = (const float*)d_in[11];
    const float* W1    = (const float*)d_in[12];
    const float* W2    = (const float*)d_in[13];
    const float* ln2g  = (const float*)d_in[14];
    const float* ln2b  = (const float*)d_in[15];
    const float* peW1  = (const float*)d_in[16];
    const float* pbg   = (const float*)d_in[17];
    const float* pbb   = (const float*)d_in[18];
    const float* pbm   = (const float*)d_in[19];
    const float* pbv   = (const float*)d_in[20];
    const float* peW2  = (const float*)d_in[21];
    float* out = (float*)d_out;

    float *q, *qpos, *feat, *vv, *b1, *b2, *off, *awl;
    cudaGetSymbolAddress((void**)&q,    g_q);
    cudaGetSymbolAddress((void**)&qpos, g_qpos);
    cudaGetSymbolAddress((void**)&feat, g_feat);
    cudaGetSymbolAddress((void**)&vv,   g_v);
    cudaGetSymbolAddress((void**)&b1,   g_b1);
    cudaGetSymbolAddress((void**)&b2,   g_b2);
    cudaGetSymbolAddress((void**)&off,  g_off);
    cudaGetSymbolAddress((void**)&awl,  g_awl);

    const int EL = MROWS * CH;           // 16.7M elements
    k_validity<<<dim3(NPIX / 256, BATCH), 256>>>(lidar);
    k_scan<<<BATCH, 1024>>>();
    k_ref<<<MROWS / 256, 256>>>();
    k_pack<<<EL / 256, 256>>>(lidar, q, 1);
    k_pack<<<EL / 256, 256>>>(bev, feat, 0);
    k_pe<<<EL / 256, 256>>>(peW1, pbg, pbb, pbm, pbv);

    dim3 g512(4, MROWS / 128), gSmall(1, MROWS / 128);
    // q_pos = relu(pe) @ peW2
    k_gemm<0,0,0,0><<<g512, 256>>>(b1, nullptr, peW2, nullptr, nullptr, qpos, 512, 512);

    for (int i = 0; i < LNUM; i++) {
        const float* Wvi   = Wv   + (size_t)i * CH * CH;
        const float* Woffi = Woff + (size_t)i * CH * 64;
        const float* Wawi  = Waw  + (size_t)i * CH * 32;
        const float* Wouti = Wout + (size_t)i * CH * CH;
        const float* W1i   = W1   + (size_t)i * CH * CH;
        const float* W2i   = W2   + (size_t)i * CH * CH;

        // v = feat @ Wv + bv
        k_gemm<0,1,0,0><<<g512, 256>>>(feat, nullptr, Wvi, bv + i * CH, nullptr, vv, 512, 512);
        // off = (q + qpos) @ Woff + boff ; aw logits = (q + qpos) @ Waw + baw
        k_gemm<1,1,0,0><<<gSmall, 256>>>(q, qpos, Woffi, boff + i * 64, nullptr, off, 64, 512);
        k_gemm<1,1,0,0><<<gSmall, 256>>>(q, qpos, Wawi,  baw  + i * 32, nullptr, awl, 32, 512);
        // deformable sampling -> b1
        k_sample<<<MROWS, 256>>>();
        // y = b1 @ Wout + bout + q ; q = LN1(y)
        k_gemm<0,1,1,0><<<g512, 256>>>(b1, nullptr, Wouti, bout + i * CH, q, b2, 512, 512);
        k_ln<<<MROWS, 128>>>(b2, ln1g + i * CH, ln1b + i * CH, q);
        // FFN: b1 = relu(q@W1); y2 = b1@W2 + q; q = LN2(y2)
        k_gemm<0,0,0,1><<<g512, 256>>>(q,  nullptr, W1i, nullptr, nullptr, b1, 512, 512);
        k_gemm<0,0,1,0><<<g512, 256>>>(b1, nullptr, W2i, nullptr, q,       b2, 512, 512);
        k_ln<<<MROWS, 128>>>(b2, ln2g + i * CH, ln2b + i * CH, q);
    }
    k_scatter<<<EL / 256, 256>>>(out);
}

// round 4
// speedup vs baseline: 2.6555x; 2.6555x over previous
#include <cuda_runtime.h>
#include <math.h>
#include <stdint.h>

#define BATCH 2
#define CH    512
#define HH    128
#define WW    128
#define NPIX  (HH*WW)        // 16384
#define MROWS (BATCH*NPIX)   // 32768
#define HEADS 8
#define HDIM  64
#define PTS   4
#define LNUM  6
#define NOA   96             // 64 offset cols + 32 attn cols

// ---------------- device scratch (no allocations allowed) ----------------
static __device__ float g_q   [MROWS*CH];
static __device__ float g_qpos[MROWS*CH];
static __device__ float g_feat[MROWS*CH];
static __device__ float g_v   [MROWS*CH];
static __device__ float g_b1  [MROWS*CH];
static __device__ float g_b2  [MROWS*CH];
static __device__ float g_oa  [MROWS*NOA];
static __device__ float g_ref [MROWS*2];
static __device__ float g_wcat[LNUM*CH*NOA];
static __device__ float g_bcat[LNUM*NOA];
static __device__ int   g_valid [MROWS];
static __device__ int   g_order [MROWS];
static __device__ int   g_validp[MROWS];
static __device__ int   g_rank  [MROWS];

// ---------------- tiled transpose: src[B][R][Cc] -> dst[B][Cc][R] ----------------
__global__ void k_tr(const float* __restrict__ src, float* __restrict__ dst, int R, int Cc) {
    __shared__ float t[32][33];
    int b  = blockIdx.z;
    int c0 = blockIdx.x * 32, r0 = blockIdx.y * 32;
    int tx = threadIdx.x, ty = threadIdx.y;   // 32 x 8
    const float* s = src + (size_t)b * R * Cc;
    float*       d = dst + (size_t)b * R * Cc;
    #pragma unroll
    for (int i = 0; i < 32; i += 8)
        t[ty + i][tx] = s[(size_t)(r0 + ty + i) * Cc + c0 + tx];
    __syncthreads();
    #pragma unroll
    for (int i = 0; i < 32; i += 8)
        d[(size_t)(c0 + ty + i) * R + r0 + tx] = t[tx][ty + i];
}

// ---------------- validity from row-major [B][N][C]: all 512 nonzero ----------------
__global__ void k_validity(const float* __restrict__ t) {
    int row = blockIdx.x;
    int tid = threadIdx.x;          // 128
    float4 v = *(const float4*)(t + (size_t)row * CH + tid * 4);
    int ok = (v.x != 0.0f) & (v.y != 0.0f) & (v.z != 0.0f) & (v.w != 0.0f);
    ok = __all_sync(~0u, ok);
    __shared__ int s[4];
    if ((tid & 31) == 0) s[tid >> 5] = ok;
    __syncthreads();
    if (tid == 0) g_valid[row] = s[0] & s[1] & s[2] & s[3];
}

// ---------------- stable partition (valid-first) via block scan ----------------
__global__ void k_scan() {
    int b = blockIdx.x;
    int tid = threadIdx.x;
    __shared__ int sd[1024];
    __shared__ int sbase;
    if (tid == 0) sbase = 0;
    __syncthreads();
    for (int c = 0; c < NPIX / 1024; c++) {
        int i = c * 1024 + tid;
        int v = g_valid[b * NPIX + i];
        sd[tid] = v;
        __syncthreads();
        for (int off = 1; off < 1024; off <<= 1) {
            int t = (tid >= off) ? sd[tid - off] : 0;
            __syncthreads();
            sd[tid] += t;
            __syncthreads();
        }
        g_rank[b * NPIX + i] = sbase + sd[tid] - v;
        __syncthreads();
        if (tid == 1023) sbase += sd[1023];
        __syncthreads();
    }
    int total = sbase;
    for (int c = 0; c < NPIX / 1024; c++) {
        int i = c * 1024 + tid;
        int v = g_valid[b * NPIX + i];
        int r = g_rank[b * NPIX + i];
        int pos = v ? r : (total + i - r);
        g_order [b * NPIX + pos] = i;
        g_validp[b * NPIX + pos] = v;
    }
}

__global__ void k_ref() {
    int i = blockIdx.x * blockDim.x + threadIdx.x;
    if (i >= MROWS) return;
    int n = g_order[i];
    float m = g_validp[i] ? 1.0f : 0.0f;
    g_ref[i * 2 + 0] = ((float)(n % WW) / (float)WW) * m;
    g_ref[i * 2 + 1] = ((float)(n / WW) / (float)HH) * m;
}

// ---------------- permute rows of [B][N][C] into packed order (with zeroing) ----------------
__global__ void k_permq(const float* __restrict__ t, float* __restrict__ dst) {
    int idx = blockIdx.x * blockDim.x + threadIdx.x;   // float4 units
    if (idx >= MROWS * 128) return;
    int row = idx >> 7, c4 = idx & 127;
    int n = g_order[row];
    int b = row >> 14;
    float4 v = make_float4(0.f, 0.f, 0.f, 0.f);
    if (g_validp[row])
        v = *(const float4*)(t + ((size_t)(b * NPIX + n)) * CH + c4 * 4);
    *(float4*)(dst + (size_t)row * CH + c4 * 4) = v;
}

// ---------------- scatter packed rows back to dense [B][N][C] ----------------
__global__ void k_scatrows(const float* __restrict__ q, float* __restrict__ t) {
    int idx = blockIdx.x * blockDim.x + threadIdx.x;
    if (idx >= MROWS * 128) return;
    int row = idx >> 7, c4 = idx & 127;
    int n = g_order[row];
    int b = row >> 14;
    float4 v = make_float4(0.f, 0.f, 0.f, 0.f);
    if (g_validp[row])
        v = *(const float4*)(q + (size_t)row * CH + c4 * 4);
    *(float4*)(t + ((size_t)(b * NPIX + n)) * CH + c4 * 4) = v;
}

// ---------------- concat Woff|Waw weights + biases ----------------
__global__ void k_concat(const float* __restrict__ Woff, const float* __restrict__ boff,
                         const float* __restrict__ Waw,  const float* __restrict__ baw) {
    int idx = blockIdx.x * blockDim.x + threadIdx.x;
    if (idx < LNUM * CH * NOA) {
        int j = idx % NOA, k = (idx / NOA) % CH, l = idx / (NOA * CH);
        g_wcat[idx] = (j < 64) ? Woff[((size_t)l * CH + k) * 64 + j]
                               : Waw [((size_t)l * CH + k) * 32 + (j - 64)];
    }
    if (idx < LNUM * NOA) {
        int j = idx % NOA, l = idx / NOA;
        g_bcat[idx] = (j < 64) ? boff[l * 64 + j] : baw[l * 32 + (j - 64)];
    }
}

// ---------------- positional embedding: ref@peW1 -> BN(eval) -> relu ----------------
__global__ void k_pe(const float* __restrict__ peW1, const float* __restrict__ g,
                     const float* __restrict__ bb, const float* __restrict__ m,
                     const float* __restrict__ vv) {
    int idx = blockIdx.x * blockDim.x + threadIdx.x;
    if (idx >= MROWS * CH) return;
    int c   = idx & (CH - 1);
    int row = idx >> 9;
    float rx = g_ref[row * 2], ry = g_ref[row * 2 + 1];
    float p = rx * peW1[c] + ry * peW1[CH + c];
    p = (p - m[c]) * rsqrtf(vv[c] + 1e-5f) * g[c] + bb[c];
    g_b1[idx] = fmaxf(p, 0.0f);
}

// ================= tf32 tensor-core GEMM =================
// C[M,Ncols] = (A (+A2)) @ Bw[512,Ncols] (+bias) (+Res) (relu?)
// 128x128 block tile, BK=32, 8 warps of 32x64, m16n8k8 tf32 mma.sync
__device__ __forceinline__ float to_tf32(float x) {
    float r;
    asm("cvt.rna.tf32.f32 %0, %1;" : "=f"(r) : "f"(x));
    return r;
}
__device__ __forceinline__ void mma_tf32(float c[4], const uint32_t a[4],
                                         uint32_t b0, uint32_t b1) {
    asm volatile(
        "mma.sync.aligned.m16n8k8.row.col.f32.tf32.tf32.f32 "
        "{%0,%1,%2,%3}, {%4,%5,%6,%7}, {%8,%9}, {%0,%1,%2,%3};"
        : "+f"(c[0]), "+f"(c[1]), "+f"(c[2]), "+f"(c[3])
        : "r"(a[0]), "r"(a[1]), "r"(a[2]), "r"(a[3]), "r"(b0), "r"(b1));
}

#define AS_STRIDE 36   // (4r+k)%32 all distinct -> conflict-free
#define BS_STRIDE 132  // (4k+n)%32 all distinct -> conflict-free

template<int ADD2, int BIAS, int RES, int RELU>
__global__ __launch_bounds__(256, 2)
void k_gemm(const float* __restrict__ A, const float* __restrict__ A2,
            const float* __restrict__ Bw, const float* __restrict__ bias,
            const float* __restrict__ Res, float* __restrict__ Cc, int Ncols) {
    __shared__ float As[128 * AS_STRIDE];
    __shared__ float Bs[32 * BS_STRIDE];
    int tid   = threadIdx.x;
    int warp  = tid >> 5, lane = tid & 31;
    int g     = lane >> 2, tg = lane & 3;
    int warpM = warp & 3;            // 0..3 -> rows
    int warpN = warp >> 2;           // 0..1 -> cols
    int rowBase = blockIdx.y * 128;
    int colBase = blockIdx.x * 128;

    float acc[2][8][4];
    #pragma unroll
    for (int mi = 0; mi < 2; mi++)
        #pragma unroll
        for (int ni = 0; ni < 8; ni++)
            #pragma unroll
            for (int j = 0; j < 4; j++) acc[mi][ni][j] = 0.0f;

    for (int k0 = 0; k0 < 512; k0 += 32) {
        #pragma unroll
        for (int p = 0; p < 4; p++) {
            int i2 = p * 256 + tid;
            // A tile: 128 rows x 32 k
            int r  = i2 >> 3, kc = (i2 & 7) << 2;
            float4 av = *(const float4*)(A + (size_t)(rowBase + r) * 512 + k0 + kc);
            if (ADD2) {
                float4 a2 = *(const float4*)(A2 + (size_t)(rowBase + r) * 512 + k0 + kc);
                av.x += a2.x; av.y += a2.y; av.z += a2.z; av.w += a2.w;
            }
            av.x = to_tf32(av.x); av.y = to_tf32(av.y);
            av.z = to_tf32(av.z); av.w = to_tf32(av.w);
            *(float4*)&As[r * AS_STRIDE + kc] = av;
            // B tile: 32 k x 128 n
            int kr = i2 >> 5, nc = (i2 & 31) << 2;
            float4 bv = make_float4(0.f, 0.f, 0.f, 0.f);
            if (colBase + nc < Ncols)
                bv = *(const float4*)(Bw + (size_t)(k0 + kr) * Ncols + colBase + nc);
            bv.x = to_tf32(bv.x); bv.y = to_tf32(bv.y);
            bv.z = to_tf32(bv.z); bv.w = to_tf32(bv.w);
            *(float4*)&Bs[kr * BS_STRIDE + nc] = bv;
        }
        __syncthreads();
        #pragma unroll
        for (int kk = 0; kk < 4; kk++) {
            int ks = kk * 8;
            uint32_t af[2][4];
            #pragma unroll
            for (int mi = 0; mi < 2; mi++) {
                int rb = warpM * 32 + mi * 16 + g;
                af[mi][0] = __float_as_uint(As[rb * AS_STRIDE + ks + tg]);
                af[mi][1] = __float_as_uint(As[(rb + 8) * AS_STRIDE + ks + tg]);
                af[mi][2] = __float_as_uint(As[rb * AS_STRIDE + ks + tg + 4]);
                af[mi][3] = __float_as_uint(As[(rb + 8) * AS_STRIDE + ks + tg + 4]);
            }
            #pragma unroll
            for (int ni = 0; ni < 8; ni++) {
                int nb = warpN * 64 + ni * 8 + g;
                uint32_t b0 = __float_as_uint(Bs[(ks + tg) * BS_STRIDE + nb]);
                uint32_t b1 = __float_as_uint(Bs[(ks + tg + 4) * BS_STRIDE + nb]);
                #pragma unroll
                for (int mi = 0; mi < 2; mi++)
                    mma_tf32(acc[mi][ni], af[mi], b0, b1);
            }
        }
        __syncthreads();
    }

    #pragma unroll
    for (int mi = 0; mi < 2; mi++) {
        int r0g = rowBase + warpM * 32 + mi * 16 + g;
        #pragma unroll
        for (int ni = 0; ni < 8; ni++) {
            int cg = colBase + warpN * 64 + ni * 8 + tg * 2;
            if (cg < Ncols) {
                float v0 = acc[mi][ni][0], v1 = acc[mi][ni][1];
                float v2 = acc[mi][ni][2], v3 = acc[mi][ni][3];
                if (BIAS) {
                    float bx = bias[cg], by = bias[cg + 1];
                    v0 += bx; v1 += by; v2 += bx; v3 += by;
                }
                if (RES) {
                    float2 r0 = *(const float2*)(Res + (size_t)r0g * Ncols + cg);
                    float2 r1 = *(const float2*)(Res + (size_t)(r0g + 8) * Ncols + cg);
                    v0 += r0.x; v1 += r0.y; v2 += r1.x; v3 += r1.y;
                }
                if (RELU) {
                    v0 = fmaxf(v0, 0.f); v1 = fmaxf(v1, 0.f);
                    v2 = fmaxf(v2, 0.f); v3 = fmaxf(v3, 0.f);
                }
                *(float2*)(Cc + (size_t)r0g * Ncols + cg)       = make_float2(v0, v1);
                *(float2*)(Cc + (size_t)(r0g + 8) * Ncols + cg) = make_float2(v2, v3);
            }
        }
    }
}

// ---------------- LayerNorm over C=512, one block per row ----------------
__global__ void k_ln(const float* __restrict__ y, const float* __restrict__ g,
                     const float* __restrict__ bb, float* __restrict__ out) {
    int row = blockIdx.x;
    int tid = threadIdx.x;   // 128
    float4 v = *(const float4*)(y + (size_t)row * CH + tid * 4);
    float s  = v.x + v.y + v.z + v.w;
    float sq = v.x * v.x + v.y * v.y + v.z * v.z + v.w * v.w;
    for (int o = 16; o > 0; o >>= 1) {
        s  += __shfl_down_sync(~0u, s,  o);
        sq += __shfl_down_sync(~0u, sq, o);
    }
    __shared__ float ss[4], ssq[4];
    __shared__ float smu, sinv;
    int wid = tid >> 5, lane = tid & 31;
    if (lane == 0) { ss[wid] = s; ssq[wid] = sq; }
    __syncthreads();
    if (tid == 0) {
        float S  = ss[0] + ss[1] + ss[2] + ss[3];
        float SQ = ssq[0] + ssq[1] + ssq[2] + ssq[3];
        float mu = S / CH;
        float var = SQ / CH - mu * mu;
        smu = mu; sinv = rsqrtf(var + 1e-5f);
    }
    __syncthreads();
    float mu = smu, inv = sinv;
    float4 gg = *(const float4*)(g  + tid * 4);
    float4 bv = *(const float4*)(bb + tid * 4);
    float4 o;
    o.x = (v.x - mu) * inv * gg.x + bv.x;
    o.y = (v.y - mu) * inv * gg.y + bv.y;
    o.z = (v.z - mu) * inv * gg.z + bv.z;
    o.w = (v.w - mu) * inv * gg.w + bv.w;
    *(float4*)(out + (size_t)row * CH + tid * 4) = o;
}

// ---------------- deformable sampling + softmax, one warp per (token, head) ----------------
__global__ void k_sample() {
    int row  = blockIdx.x;              // b*NPIX + p
    int b    = row >> 14;
    int h    = threadIdx.x >> 5;
    int lane = threadIdx.x & 31;
    float refx = g_ref[row * 2], refy = g_ref[row * 2 + 1];

    const float* oa = g_oa + (size_t)row * NOA;
    float l0 = oa[64 + h * 4 + 0];
    float l1 = oa[64 + h * 4 + 1];
    float l2 = oa[64 + h * 4 + 2];
    float l3 = oa[64 + h * 4 + 3];
    float mx = fmaxf(fmaxf(l0, l1), fmaxf(l2, l3));
    float e0 = expf(l0 - mx), e1 = expf(l1 - mx), e2 = expf(l2 - mx), e3 = expf(l3 - mx);
    float inv = 1.0f / (e0 + e1 + e2 + e3);

    const float* vb = g_v + (size_t)b * NPIX * CH + h * HDIM;
    float acc0 = 0.f, acc1 = 0.f;
    #pragma unroll
    for (int p = 0; p < 4; p++) {
        float wgt = (p == 0 ? e0 : p == 1 ? e1 : p == 2 ? e2 : e3) * inv;
        float ox = oa[h * 8 + p * 2 + 0];
        float oy = oa[h * 8 + p * 2 + 1];
        float x = refx * (float)WW + ox - 0.5f;
        float y = refy * (float)HH + oy - 0.5f;
        float x0f = floorf(x), y0f = floorf(y);
        float wx = x - x0f, wy = y - y0f;
        int x0 = (int)x0f, y0 = (int)y0f;
        #pragma unroll
        for (int cy = 0; cy < 2; cy++) {
            #pragma unroll
            for (int cx = 0; cx < 2; cx++) {
                int xi = x0 + cx, yi = y0 + cy;
                float wc = (cx ? wx : 1.0f - wx) * (cy ? wy : 1.0f - wy);
                float inb = (xi >= 0 && xi < WW && yi >= 0 && yi < HH) ? 1.0f : 0.0f;
                int xc = min(max(xi, 0), WW - 1);
                int yc = min(max(yi, 0), HH - 1);
                size_t base = (size_t)(yc * WW + xc) * CH;
                float w = wgt * wc * inb;
                acc0 += w * vb[base + lane];
                acc1 += w * vb[base + lane + 32];
            }
        }
    }
    g_b1[(size_t)row * CH + h * HDIM + lane]      = acc0;
    g_b1[(size_t)row * CH + h * HDIM + lane + 32] = acc1;
}

// ---------------- host ----------------
extern "C" void kernel_launch(void* const* d_in, const int* in_sizes, int n_in,
                              void* d_out, int out_size) {
    const float* bev   = (const float*)d_in[0];
    const float* lidar = (const float*)d_in[1];
    const float* Wv    = (const float*)d_in[2];
    const float* bv    = (const float*)d_in[3];
    const float* Woff  = (const float*)d_in[4];
    const float* boff  = (const float*)d_in[5];
    const float* Waw   = (const float*)d_in[6];
    const float* baw   = (const float*)d_in[7];
    const float* Wout  = (const float*)d_in[8];
    const float* bout  = (const float*)d_in[9];
    const float* ln1g  = (const float*)d_in[10];
    const float* ln1b  = (const float*)d_in[11];
    const float* W1    = (const float*)d_in[12];
    const float* W2    = (const float*)d_in[13];
    const float* ln2g  = (const float*)d_in[14];
    const float* ln2b  = (const float*)d_in[15];
    const float* peW1  = (const float*)d_in[16];
    const float* pbg   = (const float*)d_in[17];
    const float* pbb   = (const float*)d_in[18];
    const float* pbm   = (const float*)d_in[19];
    const float* pbv   = (const float*)d_in[20];
    const float* peW2  = (const float*)d_in[21];
    float* out = (float*)d_out;

    float *q, *qpos, *feat, *vv, *b1, *b2, *oa, *wcat, *bcat;
    cudaGetSymbolAddress((void**)&q,    g_q);
    cudaGetSymbolAddress((void**)&qpos, g_qpos);
    cudaGetSymbolAddress((void**)&feat, g_feat);
    cudaGetSymbolAddress((void**)&vv,   g_v);
    cudaGetSymbolAddress((void**)&b1,   g_b1);
    cudaGetSymbolAddress((void**)&b2,   g_b2);
    cudaGetSymbolAddress((void**)&oa,   g_oa);
    cudaGetSymbolAddress((void**)&wcat, g_wcat);
    cudaGetSymbolAddress((void**)&bcat, g_bcat);

    dim3 trb(32, 8);
    // lidar (B,C,N) -> b2 (B,N,C)
    k_tr<<<dim3(NPIX / 32, CH / 32, BATCH), trb>>>(lidar, b2, CH, NPIX);
    k_validity<<<MROWS, 128>>>(b2);
    k_scan<<<BATCH, 1024>>>();
    k_ref<<<MROWS / 256, 256>>>();
    k_permq<<<MROWS * 128 / 256, 256>>>(b2, q);
    // bev (B,C,N) -> feat (B,N,C)
    k_tr<<<dim3(NPIX / 32, CH / 32, BATCH), trb>>>(bev, feat, CH, NPIX);
    k_concat<<<(LNUM * CH * NOA + 255) / 256, 256>>>(Woff, boff, Waw, baw);
    k_pe<<<MROWS * CH / 256, 256>>>(peW1, pbg, pbb, pbm, pbv);

    dim3 g512(4, MROWS / 128), g96(1, MROWS / 128);
    // q_pos = relu(pe) @ peW2
    k_gemm<0,0,0,0><<<g512, 256>>>(b1, nullptr, peW2, nullptr, nullptr, qpos, 512);

    for (int i = 0; i < LNUM; i++) {
        const float* Wvi   = Wv   + (size_t)i * CH * CH;
        const float* Wcati = wcat + (size_t)i * CH * NOA;
        const float* Wouti = Wout + (size_t)i * CH * CH;
        const float* W1i   = W1   + (size_t)i * CH * CH;
        const float* W2i   = W2   + (size_t)i * CH * CH;

        // v = feat @ Wv + bv
        k_gemm<0,1,0,0><<<g512, 256>>>(feat, nullptr, Wvi, bv + i * CH, nullptr, vv, 512);
        // [off | aw-logits] = (q + qpos) @ Wcat + bcat
        k_gemm<1,1,0,0><<<g96, 256>>>(q, qpos, Wcati, bcat + i * NOA, nullptr, oa, NOA);
        // deformable sampling -> b1
        k_sample<<<MROWS, 256>>>();
        // y = b1 @ Wout + bout + q ; q = LN1(y)
        k_gemm<0,1,1,0><<<g512, 256>>>(b1, nullptr, Wouti, bout + i * CH, q, b2, 512);
        k_ln<<<MROWS, 128>>>(b2, ln1g + i * CH, ln1b + i * CH, q);
        // FFN: b1 = relu(q@W1); y2 = b1@W2 + q; q = LN2(y2)
        k_gemm<0,0,0,1><<<g512, 256>>>(q,  nullptr, W1i, nullptr, nullptr, b1, 512);
        k_gemm<0,0,1,0><<<g512, 256>>>(b1, nullptr, W2i, nullptr, q,       b2, 512);
        k_ln<<<MROWS, 128>>>(b2, ln2g + i * CH, ln2b + i * CH, q);
    }
    // q (packed) -> dense rows in b2 (B,N,C) -> transpose to out (B,C,N)
    k_scatrows<<<MROWS * 128 / 256, 256>>>(q, b2);
    k_tr<<<dim3(CH / 32, NPIX / 32, BATCH), trb>>>(b2, out, NPIX, CH);
}

// round 5
// speedup vs baseline: 2.7183x; 1.0237x over previous
#include <cuda_runtime.h>
#include <math.h>
#include <stdint.h>

#define BATCH 2
#define CH    512
#define HH    128
#define WW    128
#define NPIX  (HH*WW)        // 16384
#define MROWS (BATCH*NPIX)   // 32768
#define HEADS 8
#define HDIM  64
#define PTS   4
#define LNUM  6
#define NOA   96             // 64 offset cols + 32 attn cols

// ---------------- device scratch (no allocations allowed) ----------------
static __device__ float g_q   [MROWS*CH];
static __device__ float g_qpos[MROWS*CH];
static __device__ float g_feat[MROWS*CH];
static __device__ float g_v   [MROWS*CH];
static __device__ float g_b1  [MROWS*CH];
static __device__ float g_b2  [MROWS*CH];
static __device__ float g_oa  [MROWS*NOA];
static __device__ float g_ref [MROWS*2];
static __device__ float g_wcat[LNUM*CH*NOA];
static __device__ float g_bcat[LNUM*NOA];
static __device__ int   g_valid [MROWS];
static __device__ int   g_order [MROWS];
static __device__ int   g_validp[MROWS];
static __device__ int   g_rank  [MROWS];

// ---------------- tiled transpose: src[B][R][Cc] -> dst[B][Cc][R] ----------------
__global__ void k_tr(const float* __restrict__ src, float* __restrict__ dst, int R, int Cc) {
    __shared__ float t[32][33];
    int b  = blockIdx.z;
    int c0 = blockIdx.x * 32, r0 = blockIdx.y * 32;
    int tx = threadIdx.x, ty = threadIdx.y;   // 32 x 8
    const float* s = src + (size_t)b * R * Cc;
    float*       d = dst + (size_t)b * R * Cc;
    #pragma unroll
    for (int i = 0; i < 32; i += 8)
        t[ty + i][tx] = s[(size_t)(r0 + ty + i) * Cc + c0 + tx];
    __syncthreads();
    #pragma unroll
    for (int i = 0; i < 32; i += 8)
        d[(size_t)(c0 + ty + i) * R + r0 + tx] = t[tx][ty + i];
}

// ---------------- validity from row-major [B][N][C]: all 512 nonzero ----------------
__global__ void k_validity(const float* __restrict__ t) {
    int row = blockIdx.x;
    int tid = threadIdx.x;          // 128
    float4 v = *(const float4*)(t + (size_t)row * CH + tid * 4);
    int ok = (v.x != 0.0f) & (v.y != 0.0f) & (v.z != 0.0f) & (v.w != 0.0f);
    ok = __all_sync(~0u, ok);
    __shared__ int s[4];
    if ((tid & 31) == 0) s[tid >> 5] = ok;
    __syncthreads();
    if (tid == 0) g_valid[row] = s[0] & s[1] & s[2] & s[3];
}

// ---------------- stable partition (valid-first) via block scan ----------------
__global__ void k_scan() {
    int b = blockIdx.x;
    int tid = threadIdx.x;
    __shared__ int sd[1024];
    __shared__ int sbase;
    if (tid == 0) sbase = 0;
    __syncthreads();
    for (int c = 0; c < NPIX / 1024; c++) {
        int i = c * 1024 + tid;
        int v = g_valid[b * NPIX + i];
        sd[tid] = v;
        __syncthreads();
        for (int off = 1; off < 1024; off <<= 1) {
            int t = (tid >= off) ? sd[tid - off] : 0;
            __syncthreads();
            sd[tid] += t;
            __syncthreads();
        }
        g_rank[b * NPIX + i] = sbase + sd[tid] - v;
        __syncthreads();
        if (tid == 1023) sbase += sd[1023];
        __syncthreads();
    }
    int total = sbase;
    for (int c = 0; c < NPIX / 1024; c++) {
        int i = c * 1024 + tid;
        int v = g_valid[b * NPIX + i];
        int r = g_rank[b * NPIX + i];
        int pos = v ? r : (total + i - r);
        g_order [b * NPIX + pos] = i;
        g_validp[b * NPIX + pos] = v;
    }
}

__global__ void k_ref() {
    int i = blockIdx.x * blockDim.x + threadIdx.x;
    if (i >= MROWS) return;
    int n = g_order[i];
    float m = g_validp[i] ? 1.0f : 0.0f;
    g_ref[i * 2 + 0] = ((float)(n % WW) / (float)WW) * m;
    g_ref[i * 2 + 1] = ((float)(n / WW) / (float)HH) * m;
}

// ---------------- permute rows of [B][N][C] into packed order (with zeroing) ----------------
__global__ void k_permq(const float* __restrict__ t, float* __restrict__ dst) {
    int idx = blockIdx.x * blockDim.x + threadIdx.x;   // float4 units
    if (idx >= MROWS * 128) return;
    int row = idx >> 7, c4 = idx & 127;
    int n = g_order[row];
    int b = row >> 14;
    float4 v = make_float4(0.f, 0.f, 0.f, 0.f);
    if (g_validp[row])
        v = *(const float4*)(t + ((size_t)(b * NPIX + n)) * CH + c4 * 4);
    *(float4*)(dst + (size_t)row * CH + c4 * 4) = v;
}

// ---------------- scatter packed rows back to dense [B][N][C] ----------------
__global__ void k_scatrows(const float* __restrict__ q, float* __restrict__ t) {
    int idx = blockIdx.x * blockDim.x + threadIdx.x;
    if (idx >= MROWS * 128) return;
    int row = idx >> 7, c4 = idx & 127;
    int n = g_order[row];
    int b = row >> 14;
    float4 v = make_float4(0.f, 0.f, 0.f, 0.f);
    if (g_validp[row])
        v = *(const float4*)(q + (size_t)row * CH + c4 * 4);
    *(float4*)(t + ((size_t)(b * NPIX + n)) * CH + c4 * 4) = v;
}

// ---------------- concat Woff|Waw weights + biases ----------------
__global__ void k_concat(const float* __restrict__ Woff, const float* __restrict__ boff,
                         const float* __restrict__ Waw,  const float* __restrict__ baw) {
    int idx = blockIdx.x * blockDim.x + threadIdx.x;
    if (idx < LNUM * CH * NOA) {
        int j = idx % NOA, k = (idx / NOA) % CH, l = idx / (NOA * CH);
        g_wcat[idx] = (j < 64) ? Woff[((size_t)l * CH + k) * 64 + j]
                               : Waw [((size_t)l * CH + k) * 32 + (j - 64)];
    }
    if (idx < LNUM * NOA) {
        int j = idx % NOA, l = idx / NOA;
        g_bcat[idx] = (j < 64) ? boff[l * 64 + j] : baw[l * 32 + (j - 64)];
    }
}

// ---------------- positional embedding: ref@peW1 -> BN(eval) -> relu ----------------
__global__ void k_pe(const float* __restrict__ peW1, const float* __restrict__ g,
                     const float* __restrict__ bb, const float* __restrict__ m,
                     const float* __restrict__ vv) {
    int idx = blockIdx.x * blockDim.x + threadIdx.x;
    if (idx >= MROWS * CH) return;
    int c   = idx & (CH - 1);
    int row = idx >> 9;
    float rx = g_ref[row * 2], ry = g_ref[row * 2 + 1];
    float p = rx * peW1[c] + ry * peW1[CH + c];
    p = (p - m[c]) * rsqrtf(vv[c] + 1e-5f) * g[c] + bb[c];
    g_b1[idx] = fmaxf(p, 0.0f);
}

// ================= tf32 tensor-core GEMM, 2-stage pipelined =================
// C[M,Ncols] = (A (+A2)) @ Bw[512,Ncols] (+bias) (+Res) (relu?)
// 128x128 block tile, BK=32, 8 warps of 32x64, m16n8k8 tf32 mma.sync
__device__ __forceinline__ float to_tf32(float x) {
    float r;
    asm("cvt.rna.tf32.f32 %0, %1;" : "=f"(r) : "f"(x));
    return r;
}
__device__ __forceinline__ void mma_tf32(float c[4], const uint32_t a[4],
                                         uint32_t b0, uint32_t b1) {
    asm volatile(
        "mma.sync.aligned.m16n8k8.row.col.f32.tf32.tf32.f32 "
        "{%0,%1,%2,%3}, {%4,%5,%6,%7}, {%8,%9}, {%0,%1,%2,%3};"
        : "+f"(c[0]), "+f"(c[1]), "+f"(c[2]), "+f"(c[3])
        : "r"(a[0]), "r"(a[1]), "r"(a[2]), "r"(a[3]), "r"(b0), "r"(b1));
}

#define AS_STRIDE 36   // (4r+k)%32 all distinct -> conflict-free
#define BS_STRIDE 132  // (4k+n)%32 all distinct -> conflict-free
#define ATILE (128 * AS_STRIDE)
#define BTILE (32 * BS_STRIDE)
#define GEMM_SMEM ((2 * (ATILE + BTILE)) * (int)sizeof(float))

template<int ADD2, int BIAS, int RES, int RELU>
__global__ __launch_bounds__(256)
void k_gemm(const float* __restrict__ A, const float* __restrict__ A2,
            const float* __restrict__ Bw, const float* __restrict__ bias,
            const float* __restrict__ Res, float* __restrict__ Cc, int Ncols) {
    extern __shared__ float sm[];
    float* As = sm;              // 2 stages
    float* Bs = sm + 2 * ATILE;  // 2 stages
    int tid   = threadIdx.x;
    int warp  = tid >> 5, lane = tid & 31;
    int g     = lane >> 2, tg = lane & 3;
    int warpM = warp & 3;            // 0..3 -> rows
    int warpN = warp >> 2;           // 0..1 -> cols
    int rowBase = blockIdx.y * 128;
    int colBase = blockIdx.x * 128;

    // per-thread load geometry (4 float4 A, 4 float4 B per tile)
    int ldA_r [4], ldA_kc[4], ldB_kr[4], ldB_nc[4];
    #pragma unroll
    for (int p = 0; p < 4; p++) {
        int i2 = p * 256 + tid;
        ldA_r [p] = i2 >> 3;  ldA_kc[p] = (i2 & 7) << 2;
        ldB_kr[p] = i2 >> 5;  ldB_nc[p] = (i2 & 31) << 2;
    }

    float4 ra[4], rb[4];
    auto ldg_tile = [&](int k0) {
        #pragma unroll
        for (int p = 0; p < 4; p++) {
            float4 av = *(const float4*)(A + (size_t)(rowBase + ldA_r[p]) * 512 + k0 + ldA_kc[p]);
            if (ADD2) {
                float4 a2 = *(const float4*)(A2 + (size_t)(rowBase + ldA_r[p]) * 512 + k0 + ldA_kc[p]);
                av.x += a2.x; av.y += a2.y; av.z += a2.z; av.w += a2.w;
            }
            ra[p] = av;
            float4 bv = make_float4(0.f, 0.f, 0.f, 0.f);
            if (colBase + ldB_nc[p] < Ncols)
                bv = *(const float4*)(Bw + (size_t)(k0 + ldB_kr[p]) * Ncols + colBase + ldB_nc[p]);
            rb[p] = bv;
        }
    };
    auto sts_tile = [&](int s) {
        float* as = As + s * ATILE;
        float* bs = Bs + s * BTILE;
        #pragma unroll
        for (int p = 0; p < 4; p++) {
            float4 av = ra[p];
            av.x = to_tf32(av.x); av.y = to_tf32(av.y);
            av.z = to_tf32(av.z); av.w = to_tf32(av.w);
            *(float4*)&as[ldA_r[p] * AS_STRIDE + ldA_kc[p]] = av;
            float4 bv = rb[p];
            bv.x = to_tf32(bv.x); bv.y = to_tf32(bv.y);
            bv.z = to_tf32(bv.z); bv.w = to_tf32(bv.w);
            *(float4*)&bs[ldB_kr[p] * BS_STRIDE + ldB_nc[p]] = bv;
        }
    };

    float acc[2][8][4];
    #pragma unroll
    for (int mi = 0; mi < 2; mi++)
        #pragma unroll
        for (int ni = 0; ni < 8; ni++)
            #pragma unroll
            for (int j = 0; j < 4; j++) acc[mi][ni][j] = 0.0f;

    // prologue: stage 0
    ldg_tile(0);
    sts_tile(0);
    __syncthreads();

    #pragma unroll 1
    for (int t = 0; t < 16; t++) {
        int s = t & 1;
        if (t < 15) ldg_tile((t + 1) * 32);   // overlap with compute below
        const float* as = As + s * ATILE;
        const float* bs = Bs + s * BTILE;
        #pragma unroll
        for (int kk = 0; kk < 4; kk++) {
            int ks = kk * 8;
            uint32_t af[2][4];
            #pragma unroll
            for (int mi = 0; mi < 2; mi++) {
                int rb2 = warpM * 32 + mi * 16 + g;
                af[mi][0] = __float_as_uint(as[rb2 * AS_STRIDE + ks + tg]);
                af[mi][1] = __float_as_uint(as[(rb2 + 8) * AS_STRIDE + ks + tg]);
                af[mi][2] = __float_as_uint(as[rb2 * AS_STRIDE + ks + tg + 4]);
                af[mi][3] = __float_as_uint(as[(rb2 + 8) * AS_STRIDE + ks + tg + 4]);
            }
            #pragma unroll
            for (int ni = 0; ni < 8; ni++) {
                int nb = warpN * 64 + ni * 8 + g;
                uint32_t b0 = __float_as_uint(bs[(ks + tg) * BS_STRIDE + nb]);
                uint32_t b1 = __float_as_uint(bs[(ks + tg + 4) * BS_STRIDE + nb]);
                #pragma unroll
                for (int mi = 0; mi < 2; mi++)
                    mma_tf32(acc[mi][ni], af[mi], b0, b1);
            }
        }
        if (t < 15) sts_tile(s ^ 1);
        __syncthreads();
    }

    #pragma unroll
    for (int mi = 0; mi < 2; mi++) {
        int r0g = rowBase + warpM * 32 + mi * 16 + g;
        #pragma unroll
        for (int ni = 0; ni < 8; ni++) {
            int cg = colBase + warpN * 64 + ni * 8 + tg * 2;
            if (cg < Ncols) {
                float v0 = acc[mi][ni][0], v1 = acc[mi][ni][1];
                float v2 = acc[mi][ni][2], v3 = acc[mi][ni][3];
                if (BIAS) {
                    float bx = bias[cg], by = bias[cg + 1];
                    v0 += bx; v1 += by; v2 += bx; v3 += by;
                }
                if (RES) {
                    float2 r0 = *(const float2*)(Res + (size_t)r0g * Ncols + cg);
                    float2 r1 = *(const float2*)(Res + (size_t)(r0g + 8) * Ncols + cg);
                    v0 += r0.x; v1 += r0.y; v2 += r1.x; v3 += r1.y;
                }
                if (RELU) {
                    v0 = fmaxf(v0, 0.f); v1 = fmaxf(v1, 0.f);
                    v2 = fmaxf(v2, 0.f); v3 = fmaxf(v3, 0.f);
                }
                *(float2*)(Cc + (size_t)r0g * Ncols + cg)       = make_float2(v0, v1);
                *(float2*)(Cc + (size_t)(r0g + 8) * Ncols + cg) = make_float2(v2, v3);
            }
        }
    }
}

// ---------------- LayerNorm over C=512, one block per row ----------------
__global__ void k_ln(const float* __restrict__ y, const float* __restrict__ g,
                     const float* __restrict__ bb, float* __restrict__ out) {
    int row = blockIdx.x;
    int tid = threadIdx.x;   // 128
    float4 v = *(const float4*)(y + (size_t)row * CH + tid * 4);
    float s  = v.x + v.y + v.z + v.w;
    float sq = v.x * v.x + v.y * v.y + v.z * v.z + v.w * v.w;
    for (int o = 16; o > 0; o >>= 1) {
        s  += __shfl_down_sync(~0u, s,  o);
        sq += __shfl_down_sync(~0u, sq, o);
    }
    __shared__ float ss[4], ssq[4];
    __shared__ float smu, sinv;
    int wid = tid >> 5, lane = tid & 31;
    if (lane == 0) { ss[wid] = s; ssq[wid] = sq; }
    __syncthreads();
    if (tid == 0) {
        float S  = ss[0] + ss[1] + ss[2] + ss[3];
        float SQ = ssq[0] + ssq[1] + ssq[2] + ssq[3];
        float mu = S / CH;
        float var = SQ / CH - mu * mu;
        smu = mu; sinv = rsqrtf(var + 1e-5f);
    }
    __syncthreads();
    float mu = smu, inv = sinv;
    float4 gg = *(const float4*)(g  + tid * 4);
    float4 bv = *(const float4*)(bb + tid * 4);
    float4 o;
    o.x = (v.x - mu) * inv * gg.x + bv.x;
    o.y = (v.y - mu) * inv * gg.y + bv.y;
    o.z = (v.z - mu) * inv * gg.z + bv.z;
    o.w = (v.w - mu) * inv * gg.w + bv.w;
    *(float4*)(out + (size_t)row * CH + tid * 4) = o;
}

// ---------------- deformable sampling + softmax, one warp per (token, head) ----------------
__global__ void k_sample() {
    int row  = blockIdx.x;              // b*NPIX + p
    int b    = row >> 14;
    int h    = threadIdx.x >> 5;
    int lane = threadIdx.x & 31;
    float refx = g_ref[row * 2], refy = g_ref[row * 2 + 1];

    const float* oa = g_oa + (size_t)row * NOA;
    float l0 = oa[64 + h * 4 + 0];
    float l1 = oa[64 + h * 4 + 1];
    float l2 = oa[64 + h * 4 + 2];
    float l3 = oa[64 + h * 4 + 3];
    float mx = fmaxf(fmaxf(l0, l1), fmaxf(l2, l3));
    float e0 = expf(l0 - mx), e1 = expf(l1 - mx), e2 = expf(l2 - mx), e3 = expf(l3 - mx);
    float inv = 1.0f / (e0 + e1 + e2 + e3);

    const float* vb = g_v + (size_t)b * NPIX * CH + h * HDIM + lane * 2;
    float acc0 = 0.f, acc1 = 0.f;
    #pragma unroll
    for (int p = 0; p < 4; p++) {
        float wgt = (p == 0 ? e0 : p == 1 ? e1 : p == 2 ? e2 : e3) * inv;
        float ox = oa[h * 8 + p * 2 + 0];
        float oy = oa[h * 8 + p * 2 + 1];
        float x = refx * (float)WW + ox - 0.5f;
        float y = refy * (float)HH + oy - 0.5f;
        float x0f = floorf(x), y0f = floorf(y);
        float wx = x - x0f, wy = y - y0f;
        int x0 = (int)x0f, y0 = (int)y0f;
        #pragma unroll
        for (int cy = 0; cy < 2; cy++) {
            #pragma unroll
            for (int cx = 0; cx < 2; cx++) {
                int xi = x0 + cx, yi = y0 + cy;
                float wc = (cx ? wx : 1.0f - wx) * (cy ? wy : 1.0f - wy);
                float inb = (xi >= 0 && xi < WW && yi >= 0 && yi < HH) ? 1.0f : 0.0f;
                int xc = min(max(xi, 0), WW - 1);
                int yc = min(max(yi, 0), HH - 1);
                size_t base = (size_t)(yc * WW + xc) * CH;
                float w = wgt * wc * inb;
                float2 vv2 = *(const float2*)(vb + base);
                acc0 += w * vv2.x;
                acc1 += w * vv2.y;
            }
        }
    }
    *(float2*)(g_b1 + (size_t)row * CH + h * HDIM + lane * 2) = make_float2(acc0, acc1);
}

// ---------------- host ----------------
extern "C" void kernel_launch(void* const* d_in, const int* in_sizes, int n_in,
                              void* d_out, int out_size) {
    const float* bev   = (const float*)d_in[0];
    const float* lidar = (const float*)d_in[1];
    const float* Wv    = (const float*)d_in[2];
    const float* bv    = (const float*)d_in[3];
    const float* Woff  = (const float*)d_in[4];
    const float* boff  = (const float*)d_in[5];
    const float* Waw   = (const float*)d_in[6];
    const float* baw   = (const float*)d_in[7];
    const float* Wout  = (const float*)d_in[8];
    const float* bout  = (const float*)d_in[9];
    const float* ln1g  = (const float*)d_in[10];
    const float* ln1b  = (const float*)d_in[11];
    const float* W1    = (const float*)d_in[12];
    const float* W2    = (const float*)d_in[13];
    const float* ln2g  = (const float*)d_in[14];
    const float* ln2b  = (const float*)d_in[15];
    const float* peW1  = (const float*)d_in[16];
    const float* pbg   = (const float*)d_in[17];
    const float* pbb   = (const float*)d_in[18];
    const float* pbm   = (const float*)d_in[19];
    const float* pbv   = (const float*)d_in[20];
    const float* peW2  = (const float*)d_in[21];
    float* out = (float*)d_out;

    float *q, *qpos, *feat, *vv, *b1, *b2, *oa, *wcat, *bcat;
    cudaGetSymbolAddress((void**)&q,    g_q);
    cudaGetSymbolAddress((void**)&qpos, g_qpos);
    cudaGetSymbolAddress((void**)&feat, g_feat);
    cudaGetSymbolAddress((void**)&vv,   g_v);
    cudaGetSymbolAddress((void**)&b1,   g_b1);
    cudaGetSymbolAddress((void**)&b2,   g_b2);
    cudaGetSymbolAddress((void**)&oa,   g_oa);
    cudaGetSymbolAddress((void**)&wcat, g_wcat);
    cudaGetSymbolAddress((void**)&bcat, g_bcat);

    // opt-in smem for all GEMM instantiations (idempotent, capture-safe)
    cudaFuncSetAttribute(k_gemm<0,0,0,0>, cudaFuncAttributeMaxDynamicSharedMemorySize, GEMM_SMEM);
    cudaFuncSetAttribute(k_gemm<0,1,0,0>, cudaFuncAttributeMaxDynamicSharedMemorySize, GEMM_SMEM);
    cudaFuncSetAttribute(k_gemm<1,1,0,0>, cudaFuncAttributeMaxDynamicSharedMemorySize, GEMM_SMEM);
    cudaFuncSetAttribute(k_gemm<0,1,1,0>, cudaFuncAttributeMaxDynamicSharedMemorySize, GEMM_SMEM);
    cudaFuncSetAttribute(k_gemm<0,0,0,1>, cudaFuncAttributeMaxDynamicSharedMemorySize, GEMM_SMEM);
    cudaFuncSetAttribute(k_gemm<0,0,1,0>, cudaFuncAttributeMaxDynamicSharedMemorySize, GEMM_SMEM);

    dim3 trb(32, 8);
    // lidar (B,C,N) -> b2 (B,N,C)
    k_tr<<<dim3(NPIX / 32, CH / 32, BATCH), trb>>>(lidar, b2, CH, NPIX);
    k_validity<<<MROWS, 128>>>(b2);
    k_scan<<<BATCH, 1024>>>();
    k_ref<<<MROWS / 256, 256>>>();
    k_permq<<<MROWS * 128 / 256, 256>>>(b2, q);
    // bev (B,C,N) -> feat (B,N,C)
    k_tr<<<dim3(NPIX / 32, CH / 32, BATCH), trb>>>(bev, feat, CH, NPIX);
    k_concat<<<(LNUM * CH * NOA + 255) / 256, 256>>>(Woff, boff, Waw, baw);
    k_pe<<<MROWS * CH / 256, 256>>>(peW1, pbg, pbb, pbm, pbv);

    dim3 g512(4, MROWS / 128), g96(1, MROWS / 128);
    // q_pos = relu(pe) @ peW2
    k_gemm<0,0,0,0><<<g512, 256, GEMM_SMEM>>>(b1, nullptr, peW2, nullptr, nullptr, qpos, 512);

    for (int i = 0; i < LNUM; i++) {
        const float* Wvi   = Wv   + (size_t)i * CH * CH;
        const float* Wcati = wcat + (size_t)i * CH * NOA;
        const float* Wouti = Wout + (size_t)i * CH * CH;
        const float* W1i   = W1   + (size_t)i * CH * CH;
        const float* W2i   = W2   + (size_t)i * CH * CH;

        // v = feat @ Wv + bv
        k_gemm<0,1,0,0><<<g512, 256, GEMM_SMEM>>>(feat, nullptr, Wvi, bv + i * CH, nullptr, vv, 512);
        // [off | aw-logits] = (q + qpos) @ Wcat + bcat
        k_gemm<1,1,0,0><<<g96, 256, GEMM_SMEM>>>(q, qpos, Wcati, bcat + i * NOA, nullptr, oa, NOA);
        // deformable sampling -> b1
        k_sample<<<MROWS, 256>>>();
        // y = b1 @ Wout + bout + q ; q = LN1(y)
        k_gemm<0,1,1,0><<<g512, 256, GEMM_SMEM>>>(b1, nullptr, Wouti, bout + i * CH, q, b2, 512);
        k_ln<<<MROWS, 128>>>(b2, ln1g + i * CH, ln1b + i * CH, q);
        // FFN: b1 = relu(q@W1); y2 = b1@W2 + q; q = LN2(y2)
        k_gemm<0,0,0,1><<<g512, 256, GEMM_SMEM>>>(q,  nullptr, W1i, nullptr, nullptr, b1, 512);
        k_gemm<0,0,1,0><<<g512, 256, GEMM_SMEM>>>(b1, nullptr, W2i, nullptr, q,       b2, 512);
        k_ln<<<MROWS, 128>>>(b2, ln2g + i * CH, ln2b + i * CH, q);
    }
    // q (packed) -> dense rows in b2 (B,N,C) -> transpose to out (B,C,N)
    k_scatrows<<<MROWS * 128 / 256, 256>>>(q, b2);
    k_tr<<<dim3(CH / 32, NPIX / 32, BATCH), trb>>>(b2, out, NPIX, CH);
}